// round 4
// baseline (speedup 1.0000x reference)
#include <cuda_runtime.h>
#include <cuda_bf16.h>
#include <cstdint>

// Segment max-pool:
//   point_features: (B, C, N) float32   [d_in[0]]
//   points:         (B, N, 4) float32   [d_in[1]]  (unused)
//   box_ids_of_pts: (B, N)    int32 OR int64 (jax x64-dependent)  [d_in[2]]
//   out:            (B*S, C)  float32   S = 100
//
// Per (b, 2048-point chunk) block:
//   1. counting-sort point indices by label in SMEM (once, amortized over C)
//   2. per 4-channel group: stage 2048x4 floats to SMEM (coalesced LDG.128),
//      each (segment, channel) task reduces its point list with fmaxf over
//      LDS gathers -> ONE global atomicMax per (seg, ch, block)
// Float max via monotone-int encoding so atomicMax(int) == float max.

#define S_SEG   100
#define CHUNK   2048
#define NTHREADS 256
#define CG      4
#define TILE_PAD 8

__device__ int g_lab_is_64;   // 1 if labels are int64 (little-endian pairs)

__device__ __forceinline__ int enc_f32(float f) {
    int i = __float_as_int(f);
    return (i >= 0) ? i : (i ^ 0x7FFFFFFF);
}
// enc is an involution: decode == encode on the int bits.

// Detect label dtype from data: int64 labels in [0,100) look like
// [lab,0,lab,0,...] when viewed as int32 words.
__global__ void detect_lab_kernel(const int* __restrict__ lab32) {
    if (threadIdx.x == 0) {
        int is64 = 1;
        #pragma unroll 1
        for (int i = 0; i < 128; i++) {
            int lo = lab32[2 * i];
            int hi = lab32[2 * i + 1];
            if (hi != 0 || lo < 0 || lo >= S_SEG) { is64 = 0; break; }
        }
        g_lab_is_64 = is64;
    }
}

__global__ void init_out_kernel(int* __restrict__ outI, int n) {
    int i = blockIdx.x * blockDim.x + threadIdx.x;
    if (i < n) outI[i] = 0x807FFFFF;  // enc(-inf)
}

__global__ void decode_out_kernel(float* __restrict__ outF, int n) {
    int i = blockIdx.x * blockDim.x + threadIdx.x;
    if (i < n) {
        int v = __float_as_int(outF[i]);
        outF[i] = __int_as_float((v >= 0) ? v : (v ^ 0x7FFFFFFF));
    }
}

__global__ __launch_bounds__(NTHREADS)
void seg_max_kernel(const float* __restrict__ pf,
                    const int* __restrict__ lab32,
                    int* __restrict__ outI,
                    int C, int N) {
    __shared__ __align__(16) float s_tile[CG][CHUNK + TILE_PAD];
    __shared__ __align__(16) unsigned short s_lab[CHUNK];
    __shared__ __align__(16) unsigned short s_idx[CHUNK];
    __shared__ int s_cnt[S_SEG];
    __shared__ int s_off[S_SEG + 1];
    __shared__ int s_cur[S_SEG];

    const int tid = threadIdx.x;
    const int b = blockIdx.y;
    const int n0 = blockIdx.x * CHUNK;
    const int len = min(CHUNK, N - n0);
    const int is64 = g_lab_is_64;

    for (int s = tid; s < S_SEG; s += NTHREADS) s_cnt[s] = 0;
    __syncthreads();

    // ---- load labels + histogram (dtype-agnostic) ----
    {
        const size_t base = (size_t)b * N + n0;
        for (int i = tid; i < len; i += NTHREADS) {
            long long l;
            if (is64) {
                int lo = lab32[(base + i) * 2];
                int hi = lab32[(base + i) * 2 + 1];
                l = ((long long)hi << 32) | (unsigned int)lo;
            } else {
                l = lab32[base + i];
            }
            if (l >= 0 && l < S_SEG) {
                s_lab[i] = (unsigned short)l;
                atomicAdd(&s_cnt[(int)l], 1);
            } else {
                s_lab[i] = 0xFFFF;
            }
        }
    }
    __syncthreads();

    // ---- exclusive scan over 100 bins ----
    if (tid == 0) {
        int run = 0;
        #pragma unroll 4
        for (int s = 0; s < S_SEG; s++) { s_off[s] = run; run += s_cnt[s]; }
        s_off[S_SEG] = run;
    }
    __syncthreads();
    for (int s = tid; s < S_SEG; s += NTHREADS) s_cur[s] = s_off[s];
    __syncthreads();

    // ---- scatter indices into label-sorted order ----
    for (int i = tid; i < len; i += NTHREADS) {
        unsigned short l = s_lab[i];
        if (l != 0xFFFF) {
            int pos = atomicAdd(&s_cur[l], 1);
            s_idx[pos] = (unsigned short)i;
        }
    }
    __syncthreads();

    // ---- channel groups ----
    for (int cg = 0; cg < C; cg += CG) {
        const int len4 = len >> 2;
        #pragma unroll
        for (int cl = 0; cl < CG; cl++) {
            const float* src = pf + (((size_t)b * C + (cg + cl)) * N + n0);
            const float4* src4 = (const float4*)src;
            float4* dst4 = (float4*)&s_tile[cl][0];
            for (int i = tid; i < len4; i += NTHREADS) dst4[i] = src4[i];
            for (int i = (len4 << 2) + tid; i < len; i += NTHREADS)
                s_tile[cl][i] = src[i];
        }
        __syncthreads();

        for (int task = tid; task < S_SEG * CG; task += NTHREADS) {
            const int seg = task >> 2;       // CG == 4
            const int cl = task & (CG - 1);
            const int p0 = s_off[seg];
            const int p1 = s_off[seg + 1];
            if (p0 < p1) {
                float m = -__int_as_float(0x7F800000);  // -inf
                const float* row = &s_tile[cl][0];
                for (int p = p0; p < p1; p++)
                    m = fmaxf(m, row[s_idx[p]]);
                atomicMax(&outI[((size_t)(b * S_SEG + seg)) * C + cg + cl],
                          enc_f32(m));
            }
        }
        __syncthreads();
    }
}

extern "C" void kernel_launch(void* const* d_in, const int* in_sizes, int n_in,
                              void* d_out, int out_size) {
    const float* pf = (const float*)d_in[0];
    const int* lab32 = (const int*)d_in[2];

    const int pf_elems = in_sizes[0];      // B*C*N
    const int lab_elems = in_sizes[2];     // B*N
    const int C = pf_elems / lab_elems;    // 128
    const int B = out_size / (S_SEG * C);  // 8
    const int N = lab_elems / B;           // 65536

    int* outI = (int*)d_out;
    float* outF = (float*)d_out;

    detect_lab_kernel<<<1, 32>>>(lab32);

    const int initBlocks = (out_size + 255) / 256;
    init_out_kernel<<<initBlocks, 256>>>(outI, out_size);

    const int numChunks = (N + CHUNK - 1) / CHUNK;
    dim3 grid(numChunks, B);
    seg_max_kernel<<<grid, NTHREADS>>>(pf, lab32, outI, C, N);

    decode_out_kernel<<<initBlocks, 256>>>(outF, out_size);
}

// round 5
// speedup vs baseline: 1.4835x; 1.4835x over previous
#include <cuda_runtime.h>
#include <cuda_bf16.h>
#include <cstdint>

// Segment max-pool, double-buffered:
//   point_features: (B, C, N) float32   [d_in[0]]
//   box_ids_of_pts: (B, N)    int32/int64 (auto-detected)  [d_in[2]]
//   out:            (B*S, C)  float32   S = 100
//
// Per (b, 2048-pt chunk) block: counting-sort indices by label once; then for
// each 2-channel group, cp.async-prefetch the NEXT group's tile while reducing
// the CURRENT one (fmaxf over LDS gathers), one encoded-int atomicMax per
// (seg, ch, block). Float max via monotone-int encoding.

#define S_SEG    100
#define CHUNK    2048
#define NTHREADS 256
#define CG       2
#define TILE_PAD 8

__device__ int g_lab_is_64;

__device__ __forceinline__ int enc_f32(float f) {
    int i = __float_as_int(f);
    return (i >= 0) ? i : (i ^ 0x7FFFFFFF);
}

__device__ __forceinline__ void cp_async16(void* smem_dst, const void* gmem_src) {
    unsigned sa = (unsigned)__cvta_generic_to_shared(smem_dst);
    asm volatile("cp.async.cg.shared.global [%0], [%1], 16;\n"
                 :: "r"(sa), "l"(gmem_src) : "memory");
}

// init output to enc(-inf); block0/thread0 also detects label dtype:
// int64 labels in [0,100) look like [lab,0,lab,0,...] as int32 words.
__global__ void init_out_kernel(int* __restrict__ outI, int n,
                                const int* __restrict__ lab32) {
    int i = blockIdx.x * blockDim.x + threadIdx.x;
    if (i < n) outI[i] = 0x807FFFFF;
    if (blockIdx.x == 0 && threadIdx.x == 0) {
        int is64 = 1;
        #pragma unroll 1
        for (int k = 0; k < 128; k++) {
            int lo = lab32[2 * k], hi = lab32[2 * k + 1];
            if (hi != 0 || lo < 0 || lo >= S_SEG) { is64 = 0; break; }
        }
        g_lab_is_64 = is64;
    }
}

__global__ void decode_out_kernel(float* __restrict__ outF, int n) {
    int i = blockIdx.x * blockDim.x + threadIdx.x;
    if (i < n) {
        int v = __float_as_int(outF[i]);
        outF[i] = __int_as_float((v >= 0) ? v : (v ^ 0x7FFFFFFF));
    }
}

__global__ __launch_bounds__(NTHREADS)
void seg_max_kernel(const float* __restrict__ pf,
                    const int* __restrict__ lab32,
                    int* __restrict__ outI,
                    int C, int N) {
    __shared__ __align__(16) float s_tile[2][CG][CHUNK + TILE_PAD];
    __shared__ __align__(16) unsigned short s_lab[CHUNK];
    __shared__ __align__(16) unsigned short s_idx[CHUNK];
    __shared__ int s_cnt[S_SEG];
    __shared__ int s_off[S_SEG + 1];
    __shared__ int s_cur[S_SEG];

    const int tid = threadIdx.x;
    const int b = blockIdx.y;
    const int n0 = blockIdx.x * CHUNK;
    const int len = min(CHUNK, N - n0);
    const int is64 = g_lab_is_64;

    for (int s = tid; s < S_SEG; s += NTHREADS) s_cnt[s] = 0;
    __syncthreads();

    // ---- labels + histogram (dtype-agnostic) ----
    {
        const size_t base = (size_t)b * N + n0;
        for (int i = tid; i < len; i += NTHREADS) {
            long long l;
            if (is64) {
                int2 w = ((const int2*)lab32)[base + i];
                l = ((long long)w.y << 32) | (unsigned int)w.x;
            } else {
                l = lab32[base + i];
            }
            if (l >= 0 && l < S_SEG) {
                s_lab[i] = (unsigned short)l;
                atomicAdd(&s_cnt[(int)l], 1);
            } else {
                s_lab[i] = 0xFFFF;
            }
        }
    }
    __syncthreads();

    if (tid == 0) {
        int run = 0;
        #pragma unroll 4
        for (int s = 0; s < S_SEG; s++) { s_off[s] = run; run += s_cnt[s]; }
        s_off[S_SEG] = run;
    }
    __syncthreads();
    for (int s = tid; s < S_SEG; s += NTHREADS) s_cur[s] = s_off[s];
    __syncthreads();

    for (int i = tid; i < len; i += NTHREADS) {
        unsigned short l = s_lab[i];
        if (l != 0xFFFF) {
            int pos = atomicAdd(&s_cur[l], 1);
            s_idx[pos] = (unsigned short)i;
        }
    }
    __syncthreads();

    // ---- double-buffered channel groups ----
    const int nGroups = C / CG;
    const int lenAligned = len & ~3;
    const int nVec = (CHUNK / 4) * CG;   // 16B chunks per group

    // stage group g into buffer buf (cp.async + commit)
    auto stage = [&](int g, int buf) {
        const int ch0 = g * CG;
        #pragma unroll 2
        for (int k = tid; k < nVec; k += NTHREADS) {
            const int e = k * 4;
            const int cl = e / CHUNK;
            const int i = e & (CHUNK - 1);
            if (i < lenAligned) {
                const float* src = pf + (((size_t)b * C + ch0 + cl) * N + n0 + i);
                cp_async16(&s_tile[buf][cl][i], src);
            }
        }
        asm volatile("cp.async.commit_group;\n" ::: "memory");
    };

    stage(0, 0);

    for (int g = 0; g < nGroups; g++) {
        const int buf = g & 1;
        if (g + 1 < nGroups) {
            stage(g + 1, buf ^ 1);
            asm volatile("cp.async.wait_group 1;\n" ::: "memory");
        } else {
            asm volatile("cp.async.wait_group 0;\n" ::: "memory");
        }
        __syncthreads();

        // scalar tail (len not multiple of 4) — never taken for N=65536
        if (lenAligned < len) {
            const int ch0 = g * CG;
            for (int i = lenAligned + tid; i < len * CG; i += NTHREADS) {
                // cover both rows' tails
            }
            #pragma unroll
            for (int cl = 0; cl < CG; cl++) {
                const float* src = pf + (((size_t)b * C + ch0 + cl) * N + n0);
                for (int i = lenAligned + tid; i < len; i += NTHREADS)
                    s_tile[buf][cl][i] = src[i];
            }
            __syncthreads();
        }

        // reduce: task = (seg, channel-in-group)
        const int ch0 = g * CG;
        for (int task = tid; task < S_SEG * CG; task += NTHREADS) {
            const int seg = task >> 1;          // CG == 2
            const int cl = task & 1;
            const int p0 = s_off[seg];
            const int p1 = s_off[seg + 1];
            if (p0 < p1) {
                float m = -__int_as_float(0x7F800000);
                const float* row = &s_tile[buf][cl][0];
                #pragma unroll 4
                for (int p = p0; p < p1; p++)
                    m = fmaxf(m, row[s_idx[p]]);
                atomicMax(&outI[((size_t)(b * S_SEG + seg)) * C + ch0 + cl],
                          enc_f32(m));
            }
        }
        __syncthreads();   // buffer reused two iterations later
    }
}

extern "C" void kernel_launch(void* const* d_in, const int* in_sizes, int n_in,
                              void* d_out, int out_size) {
    const float* pf = (const float*)d_in[0];
    const int* lab32 = (const int*)d_in[2];

    const int pf_elems = in_sizes[0];      // B*C*N
    const int lab_elems = in_sizes[2];     // B*N
    const int C = pf_elems / lab_elems;    // 128
    const int B = out_size / (S_SEG * C);  // 8
    const int N = lab_elems / B;           // 65536

    int* outI = (int*)d_out;
    float* outF = (float*)d_out;

    const int initBlocks = (out_size + 255) / 256;
    init_out_kernel<<<initBlocks, 256>>>(outI, out_size, lab32);

    const int numChunks = (N + CHUNK - 1) / CHUNK;
    dim3 grid(numChunks, B);
    seg_max_kernel<<<grid, NTHREADS>>>(pf, lab32, outI, C, N);

    decode_out_kernel<<<initBlocks, 256>>>(outF, out_size);
}

// round 6
// speedup vs baseline: 1.6519x; 1.1136x over previous
#include <cuda_runtime.h>
#include <cuda_bf16.h>
#include <cstdint>

// Segment max-pool, double-buffered + channel-slab parallel:
//   point_features: (B, C, N) float32   [d_in[0]]
//   box_ids_of_pts: (B, N)    int32/int64 (auto-detected)  [d_in[2]]
//   out:            (B*S, C)  float32   S = 100
//
// Grid = (chunks, B, slabs). Each block: counting-sort its 2048-pt chunk's
// labels once, then for its 32-channel slab, cp.async-prefetch group g+1
// while reducing group g (fmaxf over LDS gathers), one encoded-int atomicMax
// per (seg, half, ch, block). Float max via monotone-int encoding.

#define S_SEG    100
#define CHUNK    2048
#define NTHREADS 256
#define CG       2
#define SLABS    4
#define TILE_PAD 8

__device__ int g_lab_is_64;

__device__ __forceinline__ int enc_f32(float f) {
    int i = __float_as_int(f);
    return (i >= 0) ? i : (i ^ 0x7FFFFFFF);
}

__device__ __forceinline__ void cp_async16(void* smem_dst, const void* gmem_src) {
    unsigned sa = (unsigned)__cvta_generic_to_shared(smem_dst);
    asm volatile("cp.async.cg.shared.global [%0], [%1], 16;\n"
                 :: "r"(sa), "l"(gmem_src) : "memory");
}

// init output to enc(-inf); block0/thread0 also detects label dtype:
// int64 labels in [0,100) look like [lab,0,lab,0,...] as int32 words.
__global__ void init_out_kernel(int* __restrict__ outI, int n,
                                const int* __restrict__ lab32) {
    int i = blockIdx.x * blockDim.x + threadIdx.x;
    if (i < n) outI[i] = 0x807FFFFF;
    if (blockIdx.x == 0 && threadIdx.x == 0) {
        int is64 = 1;
        #pragma unroll 1
        for (int k = 0; k < 128; k++) {
            int lo = lab32[2 * k], hi = lab32[2 * k + 1];
            if (hi != 0 || lo < 0 || lo >= S_SEG) { is64 = 0; break; }
        }
        g_lab_is_64 = is64;
    }
}

__global__ void decode_out_kernel(float* __restrict__ outF, int n) {
    int i = blockIdx.x * blockDim.x + threadIdx.x;
    if (i < n) {
        int v = __float_as_int(outF[i]);
        outF[i] = __int_as_float((v >= 0) ? v : (v ^ 0x7FFFFFFF));
    }
}

__global__ __launch_bounds__(NTHREADS)
void seg_max_kernel(const float* __restrict__ pf,
                    const int* __restrict__ lab32,
                    int* __restrict__ outI,
                    int C, int N) {
    __shared__ __align__(16) float s_tile[2][CG][CHUNK + TILE_PAD];
    __shared__ __align__(16) unsigned short s_lab[CHUNK];
    __shared__ __align__(16) unsigned short s_idx[CHUNK];
    __shared__ int s_cnt[S_SEG];
    __shared__ int s_off[S_SEG + 1];
    __shared__ int s_cur[S_SEG];

    const int tid = threadIdx.x;
    const int b = blockIdx.y;
    const int slab = blockIdx.z;
    const int chPerSlab = C / SLABS;           // 32
    const int chBase = slab * chPerSlab;
    const int n0 = blockIdx.x * CHUNK;
    const int len = min(CHUNK, N - n0);
    const int is64 = g_lab_is_64;

    for (int s = tid; s < S_SEG; s += NTHREADS) s_cnt[s] = 0;
    __syncthreads();

    // ---- labels + histogram (dtype-agnostic) ----
    {
        const size_t base = (size_t)b * N + n0;
        for (int i = tid; i < len; i += NTHREADS) {
            long long l;
            if (is64) {
                int2 w = ((const int2*)lab32)[base + i];
                l = ((long long)w.y << 32) | (unsigned int)w.x;
            } else {
                l = lab32[base + i];
            }
            if (l >= 0 && l < S_SEG) {
                s_lab[i] = (unsigned short)l;
                atomicAdd(&s_cnt[(int)l], 1);
            } else {
                s_lab[i] = 0xFFFF;
            }
        }
    }
    __syncthreads();

    if (tid == 0) {
        int run = 0;
        #pragma unroll 4
        for (int s = 0; s < S_SEG; s++) { s_off[s] = run; run += s_cnt[s]; }
        s_off[S_SEG] = run;
    }
    __syncthreads();
    for (int s = tid; s < S_SEG; s += NTHREADS) s_cur[s] = s_off[s];
    __syncthreads();

    for (int i = tid; i < len; i += NTHREADS) {
        unsigned short l = s_lab[i];
        if (l != 0xFFFF) {
            int pos = atomicAdd(&s_cur[l], 1);
            s_idx[pos] = (unsigned short)i;
        }
    }
    __syncthreads();

    // ---- double-buffered channel groups within this slab ----
    const int nGroups = chPerSlab / CG;        // 16
    const int lenAligned = len & ~3;
    const int nVec = (CHUNK / 4) * CG;

    auto stage = [&](int g, int buf) {
        const int ch0 = chBase + g * CG;
        #pragma unroll 2
        for (int k = tid; k < nVec; k += NTHREADS) {
            const int e = k * 4;
            const int cl = e / CHUNK;
            const int i = e & (CHUNK - 1);
            if (i < lenAligned) {
                const float* src = pf + (((size_t)b * C + ch0 + cl) * N + n0 + i);
                cp_async16(&s_tile[buf][cl][i], src);
            }
        }
        asm volatile("cp.async.commit_group;\n" ::: "memory");
    };

    stage(0, 0);

    for (int g = 0; g < nGroups; g++) {
        const int buf = g & 1;
        if (g + 1 < nGroups) {
            stage(g + 1, buf ^ 1);
            asm volatile("cp.async.wait_group 1;\n" ::: "memory");
        } else {
            asm volatile("cp.async.wait_group 0;\n" ::: "memory");
        }
        __syncthreads();

        // scalar tail (len % 4 != 0) — never taken for N = 65536
        if (lenAligned < len) {
            const int ch0 = chBase + g * CG;
            #pragma unroll
            for (int cl = 0; cl < CG; cl++) {
                const float* src = pf + (((size_t)b * C + ch0 + cl) * N + n0);
                for (int i = lenAligned + tid; i < len; i += NTHREADS)
                    s_tile[buf][cl][i] = src[i];
            }
            __syncthreads();
        }

        // reduce: task = (seg, half, channel-in-group); 400 tasks
        const int ch0 = chBase + g * CG;
        for (int task = tid; task < S_SEG * 2 * CG; task += NTHREADS) {
            const int seg = task >> 2;         // 2*CG == 4 subtasks per seg
            const int sub = task & 3;
            const int cl = sub & 1;
            const int half = sub >> 1;
            const int q0 = s_off[seg];
            const int q1 = s_off[seg + 1];
            const int mid = (q0 + q1 + 1) >> 1;
            const int p0 = half ? mid : q0;
            const int p1 = half ? q1 : mid;
            if (p0 < p1) {
                float m = -__int_as_float(0x7F800000);
                const float* row = &s_tile[buf][cl][0];
                #pragma unroll 4
                for (int p = p0; p < p1; p++)
                    m = fmaxf(m, row[s_idx[p]]);
                atomicMax(&outI[((size_t)(b * S_SEG + seg)) * C + ch0 + cl],
                          enc_f32(m));
            }
        }
        __syncthreads();   // buffer reused two iterations later
    }
}

extern "C" void kernel_launch(void* const* d_in, const int* in_sizes, int n_in,
                              void* d_out, int out_size) {
    const float* pf = (const float*)d_in[0];
    const int* lab32 = (const int*)d_in[2];

    const int pf_elems = in_sizes[0];      // B*C*N
    const int lab_elems = in_sizes[2];     // B*N
    const int C = pf_elems / lab_elems;    // 128
    const int B = out_size / (S_SEG * C);  // 8
    const int N = lab_elems / B;           // 65536

    int* outI = (int*)d_out;
    float* outF = (float*)d_out;

    const int initBlocks = (out_size + 255) / 256;
    init_out_kernel<<<initBlocks, 256>>>(outI, out_size, lab32);

    const int numChunks = (N + CHUNK - 1) / CHUNK;
    dim3 grid(numChunks, B, SLABS);
    seg_max_kernel<<<grid, NTHREADS>>>(pf, lab32, outI, C, N);

    decode_out_kernel<<<initBlocks, 256>>>(outF, out_size);
}